// round 2
// baseline (speedup 1.0000x reference)
#include <cuda_runtime.h>

#define BATCH 4
#define CKD   64
#define CVD   512
#define NMEM  9216   // T*H*W = 4*48*48
#define MQ    2304   // TQ*H*W = 48*48

// Tiny scratch: per-row softmax statistics (max and sum of exp), [B][MQ].
__device__ float g_max[BATCH * MQ];
__device__ float g_sum[BATCH * MQ];

// ---------------------------------------------------------------------------
// Kernel 1: for each (b, m) compute rowmax and rowsum of exp(S/8 - rowmax)
// over all n, streaming the QK GEMM with online softmax stats (no S stored).
// Block: 64 m-rows; 256 threads as 16(n) x 16(m), 4x4 dots per n-tile of 64.
// ---------------------------------------------------------------------------
__global__ __launch_bounds__(256) void stats_kernel(const float* __restrict__ mk,
                                                    const float* __restrict__ qk) {
    __shared__ float Qs[CKD][64];   // [c][m]
    __shared__ float Ks[CKD][64];   // [c][n]
    __shared__ float RM[16][64];    // [nx][m_local]
    __shared__ float RS[16][64];

    const int b  = blockIdx.y;
    const int m0 = blockIdx.x * 64;
    const int t  = threadIdx.x;

    const float* qb = qk + (size_t)b * CKD * MQ;
    const float* kb = mk + (size_t)b * CKD * NMEM;

    // Load Q tile once: row c = t>>2, 4 float4 chunks per row-quarter.
    {
        const int c  = t >> 2;
        const int g0 = t & 3;
#pragma unroll
        for (int i = 0; i < 4; i++) {
            int col = (g0 + 4 * i) * 4;
            *(float4*)&Qs[c][col] = *(const float4*)&qb[(size_t)c * MQ + m0 + col];
        }
    }

    const int nx = t & 15;
    const int my = t >> 4;

    float rm[4], rs[4];
#pragma unroll
    for (int i = 0; i < 4; i++) { rm[i] = -3.4e38f; rs[i] = 0.0f; }

    for (int n0 = 0; n0 < NMEM; n0 += 64) {
        __syncthreads();   // protect Ks from previous iteration's readers
        {
            const int c  = t >> 2;
            const int g0 = t & 3;
#pragma unroll
            for (int i = 0; i < 4; i++) {
                int col = (g0 + 4 * i) * 4;
                *(float4*)&Ks[c][col] = *(const float4*)&kb[(size_t)c * NMEM + n0 + col];
            }
        }
        __syncthreads();

        float acc[4][4] = {};
#pragma unroll 16
        for (int k = 0; k < CKD; k++) {
            float4 a = *(float4*)&Qs[k][my * 4];
            float4 v = *(float4*)&Ks[k][nx * 4];
            float av[4] = {a.x, a.y, a.z, a.w};
            float bv[4] = {v.x, v.y, v.z, v.w};
#pragma unroll
            for (int i = 0; i < 4; i++)
#pragma unroll
                for (int j = 0; j < 4; j++)
                    acc[i][j] += av[i] * bv[j];
        }

        // Online (max, sum) update per m row handled by this thread.
#pragma unroll
        for (int i = 0; i < 4; i++) {
            float s0 = acc[i][0] * 0.125f, s1 = acc[i][1] * 0.125f;
            float s2 = acc[i][2] * 0.125f, s3 = acc[i][3] * 0.125f;
            float tmax = fmaxf(fmaxf(s0, s1), fmaxf(s2, s3));
            float nm = fmaxf(rm[i], tmax);
            float part = __expf(s0 - nm) + __expf(s1 - nm) +
                         __expf(s2 - nm) + __expf(s3 - nm);
            rs[i] = rs[i] * __expf(rm[i] - nm) + part;
            rm[i] = nm;
        }
    }

    // Cross-thread reduce over the 16 n-groups sharing each m row.
#pragma unroll
    for (int i = 0; i < 4; i++) {
        RM[nx][my * 4 + i] = rm[i];
        RS[nx][my * 4 + i] = rs[i];
    }
    __syncthreads();
    if (t < 64) {
        float M = -3.4e38f;
#pragma unroll
        for (int j = 0; j < 16; j++) M = fmaxf(M, RM[j][t]);
        float S = 0.0f;
#pragma unroll
        for (int j = 0; j < 16; j++) S += RS[j][t] * __expf(RM[j][t] - M);
        g_max[b * MQ + m0 + t] = M;
        g_sum[b * MQ + m0 + t] = S;
    }
}

// ---------------------------------------------------------------------------
// Kernel 2 (fused): per (b, 32-query tile), stream n in tiles of 32:
//   - recompute S sub-tile (K=64), apply exp(s/8 - max)/sum -> P in smem
//   - accumulate O[cv 512][m 32] += mv[cv][n] * P[n][m]
// 256 threads: S phase as 8(n)x32(m); PV phase as 64(cv)x4(m), 8x8 per thread.
// Dynamic smem: Qs 64x32 | Ks 64x32 | Ps 32x36 | Vs 32x516 (transposed mv).
// ---------------------------------------------------------------------------
#define SM_QS   0
#define SM_KS   2048
#define SM_PS   4096          // stride 36 (144B, 16B-aligned rows)
#define SM_VS   5248          // stride 516 (2064B, 16B-aligned rows)
#define SM_TOT  (5248 + 32 * 516)   // 21760 floats = 87040 bytes

__global__ __launch_bounds__(256) void pv_kernel(const float* __restrict__ mk,
                                                 const float* __restrict__ qk,
                                                 const float* __restrict__ mv,
                                                 float* __restrict__ out) {
    extern __shared__ float sm[];
    float* Qs = sm + SM_QS;   // [c][m]   stride 32
    float* Ks = sm + SM_KS;   // [c][n]   stride 32
    float* Ps = sm + SM_PS;   // [n][m]   stride 36
    float* Vs = sm + SM_VS;   // [n][cv]  stride 516

    const int b  = blockIdx.y;
    const int m0 = blockIdx.x * 32;
    const int t  = threadIdx.x;

    const float* qb = qk + (size_t)b * CKD * MQ;
    const float* kb = mk + (size_t)b * CKD * NMEM;
    const float* vb = mv + (size_t)b * CVD * NMEM;

    // Load Q tile once: 64 rows x 32 floats, 8 floats per thread.
    {
        const int c = t >> 2;
        const int o = (t & 3) * 8;
        const float* p = &qb[(size_t)c * MQ + m0 + o];
        *(float4*)&Qs[c * 32 + o]     = *(const float4*)&p[0];
        *(float4*)&Qs[c * 32 + o + 4] = *(const float4*)&p[4];
    }

    // Softmax stats for this thread's S-phase row.
    const int sy = t & 31;        // m index in tile
    const int sx = t >> 5;        // n group (4 n each)
    const float row_max = g_max[b * MQ + m0 + sy];
    const float row_inv = 1.0f / g_sum[b * MQ + m0 + sy];

    // PV mapping: 8 cv x 8 m per thread.
    const int cvg = t >> 2;       // cv base = cvg*8
    const int mg  = t & 3;        // m  base = mg*8
    float acc[8][8] = {};

    for (int n0 = 0; n0 < NMEM; n0 += 32) {
        __syncthreads();   // protect Ks/Vs/Ps from previous iteration

        // Load K tile: 64 rows x 32 floats.
        {
            const int c = t >> 2;
            const int o = (t & 3) * 8;
            const float* p = &kb[(size_t)c * NMEM + n0 + o];
            *(float4*)&Ks[c * 32 + o]     = *(const float4*)&p[0];
            *(float4*)&Ks[c * 32 + o + 4] = *(const float4*)&p[4];
        }
        // Load mv tile transposed: Vs[n][cv]. 8 threads per cv row (coalesced).
        {
            const int q  = t & 7;          // float4 column group
            const int c0 = t >> 3;         // cv base (stride 32)
#pragma unroll
            for (int i = 0; i < 16; i++) {
                int cv = c0 + i * 32;
                float4 x = *(const float4*)&vb[(size_t)cv * NMEM + n0 + q * 4];
                Vs[(q * 4 + 0) * 516 + cv] = x.x;
                Vs[(q * 4 + 1) * 516 + cv] = x.y;
                Vs[(q * 4 + 2) * 516 + cv] = x.z;
                Vs[(q * 4 + 3) * 516 + cv] = x.w;
            }
        }
        __syncthreads();

        // S phase: this thread computes S[m=sy][n = sx*4 .. sx*4+3].
        {
            float s0 = 0.f, s1 = 0.f, s2 = 0.f, s3 = 0.f;
#pragma unroll 16
            for (int k = 0; k < CKD; k++) {
                float qv = Qs[k * 32 + sy];
                float4 kv = *(float4*)&Ks[k * 32 + sx * 4];
                s0 += qv * kv.x; s1 += qv * kv.y;
                s2 += qv * kv.z; s3 += qv * kv.w;
            }
            Ps[(sx * 4 + 0) * 36 + sy] = __expf(s0 * 0.125f - row_max) * row_inv;
            Ps[(sx * 4 + 1) * 36 + sy] = __expf(s1 * 0.125f - row_max) * row_inv;
            Ps[(sx * 4 + 2) * 36 + sy] = __expf(s2 * 0.125f - row_max) * row_inv;
            Ps[(sx * 4 + 3) * 36 + sy] = __expf(s3 * 0.125f - row_max) * row_inv;
        }
        __syncthreads();

        // PV phase: acc[cv 8][m 8] += Vs[k][cv] * Ps[k][m]
#pragma unroll 8
        for (int k = 0; k < 32; k++) {
            float4 a0 = *(float4*)&Vs[k * 516 + cvg * 8];
            float4 a1 = *(float4*)&Vs[k * 516 + cvg * 8 + 4];
            float4 p0 = *(float4*)&Ps[k * 36 + mg * 8];
            float4 p1 = *(float4*)&Ps[k * 36 + mg * 8 + 4];
            float av[8] = {a0.x, a0.y, a0.z, a0.w, a1.x, a1.y, a1.z, a1.w};
            float pv[8] = {p0.x, p0.y, p0.z, p0.w, p1.x, p1.y, p1.z, p1.w};
#pragma unroll
            for (int i = 0; i < 8; i++)
#pragma unroll
                for (int j = 0; j < 8; j++)
                    acc[i][j] += av[i] * pv[j];
        }
    }

    // Store: out[b][cv][m], TQ=1 so reference transpose is a no-op.
#pragma unroll
    for (int i = 0; i < 8; i++) {
        float* op = out + ((size_t)b * CVD + cvg * 8 + i) * MQ + m0 + mg * 8;
        *(float4*)&op[0] = make_float4(acc[i][0], acc[i][1], acc[i][2], acc[i][3]);
        *(float4*)&op[4] = make_float4(acc[i][4], acc[i][5], acc[i][6], acc[i][7]);
    }
}

// ---------------------------------------------------------------------------
extern "C" void kernel_launch(void* const* d_in, const int* in_sizes, int n_in,
                              void* d_out, int out_size) {
    const float* mk = (const float*)d_in[0];
    const float* qk = (const float*)d_in[1];
    const float* mv = (const float*)d_in[2];
    float* out = (float*)d_out;

    cudaFuncSetAttribute(pv_kernel, cudaFuncAttributeMaxDynamicSharedMemorySize,
                         SM_TOT * 4);

    dim3 g1(MQ / 64, BATCH);              // 36 x 4
    stats_kernel<<<g1, 256>>>(mk, qk);

    dim3 g2(MQ / 32, BATCH);              // 72 x 4
    pv_kernel<<<g2, 256, SM_TOT * 4>>>(mk, qk, mv, out);
}